// round 16
// baseline (speedup 1.0000x reference)
#include <cuda_runtime.h>
#include <cuda_bf16.h>
#include <math.h>

// Problem constants
#define DMODEL 256
#define TLEN   64
#define NHEADS 8
#define DHEAD  32
#define SEQS   1024                 // B*H*W
#define TOKENS (SEQS * TLEN)        // 65536
#define OUT_ELEMS  ((long)TOKENS * DMODEL)             // 16,777,216
#define ATTN_ELEMS ((long)SEQS * NHEADS * TLEN * TLEN) // 33,554,432
#define QSCALE 0.17677669529663687f                    // 1/sqrt(32)

// ---------------------------------------------------------------------------
// Device scratch (no allocation allowed)
// ---------------------------------------------------------------------------
__device__ __align__(128) unsigned short g_qh[TOKENS * DMODEL];
__device__ __align__(128) unsigned short g_ql[TOKENS * DMODEL];
__device__ __align__(128) unsigned short g_kh[TOKENS * DMODEL];
__device__ __align__(128) unsigned short g_kl[TOKENS * DMODEL];
__device__ __align__(128) unsigned short g_vh[TOKENS * DMODEL];
__device__ __align__(128) unsigned short g_vl[TOKENS * DMODEL];
__device__ __align__(128) float g_ctx[TOKENS * DMODEL];  // merged heads [token][d]
__device__ __align__(128) unsigned short g_wt_hi[4][DMODEL * DMODEL];
__device__ __align__(128) unsigned short g_wt_lo[4][DMODEL * DMODEL];

// ---------------------------------------------------------------------------
// Helpers (all baseline sm_80/90 PTX)
// ---------------------------------------------------------------------------
__device__ __forceinline__ unsigned smem_u32(const void* p) {
    unsigned a;
    asm("{ .reg .u64 t; cvta.to.shared.u64 t, %1; cvt.u32.u64 %0, t; }"
        : "=r"(a) : "l"(p));
    return a;
}
__device__ __forceinline__ unsigned pack_bf2(float e0, float e1) {
    unsigned r;
    asm("cvt.rn.bf16x2.f32 %0, %1, %2;" : "=r"(r) : "f"(e1), "f"(e0));
    return r;
}
__device__ __forceinline__ float bf_round(float x) {
    return __bfloat162float(__float2bfloat16_rn(x));
}
__device__ __forceinline__ void ldmx4(unsigned* r, unsigned addr) {
    asm volatile("ldmatrix.sync.aligned.m8n8.x4.shared.b16 {%0,%1,%2,%3}, [%4];"
                 : "=r"(r[0]), "=r"(r[1]), "=r"(r[2]), "=r"(r[3]) : "r"(addr));
}
__device__ __forceinline__ void mma16816(float* d, const unsigned* a, const unsigned* b) {
    asm volatile(
        "mma.sync.aligned.m16n8k16.row.col.f32.bf16.bf16.f32 "
        "{%0,%1,%2,%3}, {%4,%5,%6,%7}, {%8,%9}, {%0,%1,%2,%3};"
        : "+f"(d[0]), "+f"(d[1]), "+f"(d[2]), "+f"(d[3])
        : "r"(a[0]), "r"(a[1]), "r"(a[2]), "r"(a[3]), "r"(b[0]), "r"(b[1]));
}
__device__ __forceinline__ void cp_async16(unsigned dst, const void* src) {
    asm volatile("cp.async.cg.shared.global [%0], [%1], 16;"
                 :: "r"(dst), "l"(src) : "memory");
}
__device__ __forceinline__ void cp_commit() {
    asm volatile("cp.async.commit_group;" ::: "memory");
}
__device__ __forceinline__ void cp_wait0() {
    asm volatile("cp.async.wait_group 0;" ::: "memory");
}
__device__ __forceinline__ void split2(float x0, float x1, ushort2& h, ushort2& l) {
    __nv_bfloat16 h0 = __float2bfloat16_rn(x0);
    __nv_bfloat16 h1 = __float2bfloat16_rn(x1);
    h.x = __bfloat16_as_ushort(h0);
    h.y = __bfloat16_as_ushort(h1);
    l.x = __bfloat16_as_ushort(__float2bfloat16_rn(x0 - __bfloat162float(h0)));
    l.y = __bfloat16_as_ushort(__float2bfloat16_rn(x1 - __bfloat162float(h1)));
}

// ---------------------------------------------------------------------------
// Weight prep (q-scale folded into wq)
// ---------------------------------------------------------------------------
__global__ void prep_weights_kernel(const float* __restrict__ wq,
                                    const float* __restrict__ wk,
                                    const float* __restrict__ wv,
                                    const float* __restrict__ wo)
{
    int i = blockIdx.x * 256 + threadIdx.x;
    int g = i >> 16;
    int r = i & 65535;
    int n = r >> 8;
    int k = r & 255;
    const float* W = (g == 0) ? wq : (g == 1) ? wk : (g == 2) ? wv : wo;
    float x = W[k * DMODEL + n];
    if (g == 0) x *= QSCALE;
    __nv_bfloat16 hb = __float2bfloat16_rn(x);
    float hf = __bfloat162float(hb);
    __nv_bfloat16 lb = __float2bfloat16_rn(x - hf);
    g_wt_hi[g][(n << 8) | k] = __bfloat16_as_ushort(hb);
    g_wt_lo[g][(n << 8) | k] = __bfloat16_as_ushort(lb);
}

// ---------------------------------------------------------------------------
// Pipelined mma.sync GEMM v2: CTA tile 128x256 (full N), 512 threads,
// warp tile 32x64. Double-buffered dynamic smem; B via cp.async; A via
// register prefetch + convert. D += Ah*Bh + Al*Bh + Ah*Bl.
// Stage layout (bytes): Ah@0 (10240), Al@10240, Bh@20480 (20480), Bl@40960.
// ---------------------------------------------------------------------------
#define SROW 40
#define ST_AL 10240
#define ST_BH 20480
#define ST_BL 40960
#define STAGE_BYTES 61440
#define SMEM_GEMM (2 * STAGE_BYTES)

template <int MODE>
__device__ __forceinline__ void gemm_mma(const float* __restrict__ A, int g,
                                         const float* __restrict__ bias,
                                         float bscale,
                                         float* __restrict__ Cf,
                                         unsigned short* __restrict__ Ch,
                                         unsigned short* __restrict__ Cl)
{
    extern __shared__ char dsm[];
    __shared__ float sbias[DMODEL];

    const int tid  = threadIdx.x;
    const int lane = tid & 31;
    const int wid  = tid >> 5;
    const int m0   = blockIdx.x * 128;
    const int warp_m = (wid >> 2) * 32;   // 0,32,64,96
    const int warp_n = (wid & 3) * 64;    // 0,64,128,192

    const unsigned short* __restrict__ WH = g_wt_hi[g];
    const unsigned short* __restrict__ WL = g_wt_lo[g];

    if (tid < DMODEL) sbias[tid] = bias[tid] * bscale;

    const unsigned smB = smem_u32(dsm);

    // A-load indices (2 float4 / thread)
    const int ar0 = tid >> 3;               // [0,64)
    const int ac0 = tid & 7;
    const int ar1 = (tid + 512) >> 3;       // [64,128)

    // ldmatrix lane-address components
    const int lg = lane >> 3;
    const int lr = lane & 7;
    const int aRow = lr + (lg & 1) * 8;
    const int aKb  = (lg >> 1) * 16;
    const int bRow = lr + (lg >> 1) * 8;
    const int bKb  = (lg & 1) * 16;

    float acc[2][8][4];
#pragma unroll
    for (int mi = 0; mi < 2; mi++)
#pragma unroll
        for (int nt = 0; nt < 8; nt++)
#pragma unroll
            for (int r = 0; r < 4; r++) acc[mi][nt][r] = 0.0f;

    float4 pa0, pa1;

    // ---- prologue: fill stage 0
    {
        const int k0 = 0;
        pa0 = *(const float4*)&A[(size_t)(m0 + ar0) * DMODEL + k0 + ac0 * 4];
        pa1 = *(const float4*)&A[(size_t)(m0 + ar1) * DMODEL + k0 + ac0 * 4];
#pragma unroll
        for (int i = 0; i < 4; i++) {
            int idx = tid + i * 512;        // [0,2048)
            int buf = idx >> 10;
            int rem = idx & 1023;
            int row = rem >> 2;
            int u   = rem & 3;
            const unsigned short* src = ((buf == 0) ? WH : WL) + (size_t)row * DMODEL + k0 + u * 8;
            cp_async16(smB + (buf == 0 ? ST_BH : ST_BL) + row * (SROW * 2) + u * 16, src);
        }
        cp_commit();
        // convert A into stage 0
        {
            float hx = bf_round(pa0.x), hy = bf_round(pa0.y);
            float hz = bf_round(pa0.z), hw = bf_round(pa0.w);
            unsigned off = (unsigned)(ar0 * (SROW * 2) + ac0 * 8);
            *(uint2*)(dsm + off)         = make_uint2(pack_bf2(pa0.x, pa0.y), pack_bf2(pa0.z, pa0.w));
            *(uint2*)(dsm + ST_AL + off) = make_uint2(pack_bf2(pa0.x - hx, pa0.y - hy),
                                                      pack_bf2(pa0.z - hz, pa0.w - hw));
            hx = bf_round(pa1.x); hy = bf_round(pa1.y);
            hz = bf_round(pa1.z); hw = bf_round(pa1.w);
            off = (unsigned)(ar1 * (SROW * 2) + ac0 * 8);
            *(uint2*)(dsm + off)         = make_uint2(pack_bf2(pa1.x, pa1.y), pack_bf2(pa1.z, pa1.w));
            *(uint2*)(dsm + ST_AL + off) = make_uint2(pack_bf2(pa1.x - hx, pa1.y - hy),
                                                      pack_bf2(pa1.z - hz, pa1.w - hw));
        }
        cp_wait0();
        __syncthreads();
    }

    for (int c = 0; c < 8; c++) {
        const unsigned curO = (unsigned)((c & 1) * STAGE_BYTES);
        const unsigned nxtO = curO ^ STAGE_BYTES;
        char* nxtP = dsm + nxtO;

        // prefetch next chunk (A regs + B cp.async)
        if (c < 7) {
            const int k0 = (c + 1) * 32;
            pa0 = *(const float4*)&A[(size_t)(m0 + ar0) * DMODEL + k0 + ac0 * 4];
            pa1 = *(const float4*)&A[(size_t)(m0 + ar1) * DMODEL + k0 + ac0 * 4];
#pragma unroll
            for (int i = 0; i < 4; i++) {
                int idx = tid + i * 512;
                int buf = idx >> 10;
                int rem = idx & 1023;
                int row = rem >> 2;
                int u   = rem & 3;
                const unsigned short* src = ((buf == 0) ? WH : WL) + (size_t)row * DMODEL + k0 + u * 8;
                cp_async16(smB + nxtO + (buf == 0 ? ST_BH : ST_BL) + row * (SROW * 2) + u * 16, src);
            }
            cp_commit();
        }

        // ---- mma on current stage
#pragma unroll
        for (int ks = 0; ks < 2; ks++) {
            const int kbb = ks * 32;
            unsigned afh[2][4], afl[2][4];
#pragma unroll
            for (int mi = 0; mi < 2; mi++) {
                unsigned aoff = smB + curO + (unsigned)((warp_m + mi * 16 + aRow) * (SROW * 2) + kbb + aKb);
                ldmx4(afh[mi], aoff);
                ldmx4(afl[mi], aoff + ST_AL);
            }
#pragma unroll
            for (int np = 0; np < 4; np++) {
                unsigned bfh[4], bfl[4];
                unsigned boff = smB + curO + ST_BH + (unsigned)((warp_n + np * 16 + bRow) * (SROW * 2) + kbb + bKb);
                ldmx4(bfh, boff);
                ldmx4(bfl, boff + (ST_BL - ST_BH));
#pragma unroll
                for (int mi = 0; mi < 2; mi++) {
#pragma unroll
                    for (int nj = 0; nj < 2; nj++) {
                        int nt = np * 2 + nj;
                        mma16816(acc[mi][nt], afh[mi], &bfh[nj * 2]);
                        mma16816(acc[mi][nt], afl[mi], &bfh[nj * 2]);
                        mma16816(acc[mi][nt], afh[mi], &bfl[nj * 2]);
                    }
                }
            }
        }

        // convert prefetched A into next stage
        if (c < 7) {
            float hx = bf_round(pa0.x), hy = bf_round(pa0.y);
            float hz = bf_round(pa0.z), hw = bf_round(pa0.w);
            unsigned off = (unsigned)(ar0 * (SROW * 2) + ac0 * 8);
            *(uint2*)(nxtP + off)         = make_uint2(pack_bf2(pa0.x, pa0.y), pack_bf2(pa0.z, pa0.w));
            *(uint2*)(nxtP + ST_AL + off) = make_uint2(pack_bf2(pa0.x - hx, pa0.y - hy),
                                                       pack_bf2(pa0.z - hz, pa0.w - hw));
            hx = bf_round(pa1.x); hy = bf_round(pa1.y);
            hz = bf_round(pa1.z); hw = bf_round(pa1.w);
            off = (unsigned)(ar1 * (SROW * 2) + ac0 * 8);
            *(uint2*)(nxtP + off)         = make_uint2(pack_bf2(pa1.x, pa1.y), pack_bf2(pa1.z, pa1.w));
            *(uint2*)(nxtP + ST_AL + off) = make_uint2(pack_bf2(pa1.x - hx, pa1.y - hy),
                                                       pack_bf2(pa1.z - hz, pa1.w - hw));
        }
        cp_wait0();
        __syncthreads();
    }

    // ---- epilogue
    const int qr = lane >> 2;
    const int qc = (lane & 3) * 2;
#pragma unroll
    for (int mi = 0; mi < 2; mi++) {
#pragma unroll
        for (int nt = 0; nt < 8; nt++) {
            int colg = warp_n + nt * 8 + qc;
            float b0 = sbias[colg], b1 = sbias[colg + 1];
            int r0 = m0 + warp_m + mi * 16 + qr;
            int r1 = r0 + 8;
            float x00 = acc[mi][nt][0] + b0, x01 = acc[mi][nt][1] + b1;
            float x10 = acc[mi][nt][2] + b0, x11 = acc[mi][nt][3] + b1;
            if (MODE == 0) {
                *(float2*)&Cf[(size_t)r0 * DMODEL + colg] = make_float2(x00, x01);
                *(float2*)&Cf[(size_t)r1 * DMODEL + colg] = make_float2(x10, x11);
            } else {
                int hd = colg >> 5;
                int dh = colg & 31;
                int s0 = r0 >> 6, t0 = r0 & 63;
                int s1 = r1 >> 6, t1 = r1 & 63;
                size_t b0i = (((size_t)s0 * NHEADS + hd) * TLEN + t0) * DHEAD + dh;
                size_t b1i = (((size_t)s1 * NHEADS + hd) * TLEN + t1) * DHEAD + dh;
                ushort2 h, l;
                split2(x00, x01, h, l);
                *(ushort2*)&Ch[b0i] = h;
                *(ushort2*)&Cl[b0i] = l;
                split2(x10, x11, h, l);
                *(ushort2*)&Ch[b1i] = h;
                *(ushort2*)&Cl[b1i] = l;
            }
        }
    }
}

__global__ void __launch_bounds__(512)
qkv_mma_kernel(const float* __restrict__ q, const float* __restrict__ k,
               const float* __restrict__ v,
               const float* __restrict__ bq, const float* __restrict__ bk,
               const float* __restrict__ bv)
{
    int z = blockIdx.z;
    if (z == 0)      gemm_mma<1>(q, 0, bq, QSCALE, nullptr, g_qh, g_ql);
    else if (z == 1) gemm_mma<1>(k, 1, bk, 1.0f,  nullptr, g_kh, g_kl);
    else             gemm_mma<1>(v, 2, bv, 1.0f,  nullptr, g_vh, g_vl);
}

__global__ void __launch_bounds__(512)
out_mma_kernel(const float* __restrict__ bo, float* __restrict__ C)
{
    gemm_mma<0>(g_ctx, 3, bo, 1.0f, C, nullptr, nullptr);
}

// ---------------------------------------------------------------------------
// Tensor-core attention (unchanged from passing R13 version)
// ---------------------------------------------------------------------------
#define VROW 72

__global__ void __launch_bounds__(128)
attn_mma_kernel(const float* __restrict__ mask, float* __restrict__ attn_out)
{
    __shared__ __align__(16) char sm[29952];
    unsigned short* Qh  = (unsigned short*)(sm);
    unsigned short* Ql  = (unsigned short*)(sm + 5120);
    unsigned short* Kh  = (unsigned short*)(sm + 10240);
    unsigned short* Kl  = (unsigned short*)(sm + 15360);
    float*          ls  = (float*)(sm);
    unsigned short* Vth = (unsigned short*)(sm + 20480);
    unsigned short* Vtl = (unsigned short*)(sm + 25088);
    float*          msk = (float*)(sm + 29696);

    const int head = blockIdx.x;
    const int tid  = threadIdx.x;
    const int lane = tid & 31;
    const int wid  = tid >> 5;
    const int b    = head >> 11;

    if (tid < 64) msk[tid] = mask[b * 64 + tid] * (-1e9f);

    const size_t hb = (size_t)head * (TLEN * DHEAD);

#pragma unroll
    for (int i = 0; i < 2; i++) {
        int idx = tid + i * 128;
        int r = idx >> 2;
        int u = idx & 3;
        unsigned off = (unsigned)(r * (SROW * 2) + u * 16);
        *(uint4*)((char*)Qh + off) = ((const uint4*)(g_qh + hb))[idx];
        *(uint4*)((char*)Ql + off) = ((const uint4*)(g_ql + hb))[idx];
        *(uint4*)((char*)Kh + off) = ((const uint4*)(g_kh + hb))[idx];
        *(uint4*)((char*)Kl + off) = ((const uint4*)(g_kl + hb))[idx];
    }
#pragma unroll
    for (int i = 0; i < 16; i++) {
        int idx = tid + i * 128;
        int s  = idx >> 5;
        int dh = idx & 31;
        Vth[dh * VROW + s] = g_vh[hb + idx];
        Vtl[dh * VROW + s] = g_vl[hb + idx];
    }
    __syncthreads();

    const unsigned qhB = smem_u32(Qh), qlB = smem_u32(Ql);
    const unsigned khB = smem_u32(Kh), klB = smem_u32(Kl);
    const unsigned vhB = smem_u32(Vth), vlB = smem_u32(Vtl);

    const int lg = lane >> 3;
    const int lr = lane & 7;
    const int aRow = lr + (lg & 1) * 8;
    const int aKb  = (lg >> 1) * 16;
    const int bRow = lr + (lg >> 1) * 8;
    const int bKb  = (lg & 1) * 16;

    float sacc[8][4];
#pragma unroll
    for (int nt = 0; nt < 8; nt++)
#pragma unroll
        for (int r = 0; r < 4; r++) sacc[nt][r] = 0.0f;

#pragma unroll
    for (int ks = 0; ks < 2; ks++) {
        const int kbb = ks * 32;
        unsigned ah[4], al[4];
        unsigned aoff = (unsigned)((wid * 16 + aRow) * (SROW * 2) + kbb + aKb);
        ldmx4(ah, qhB + aoff);
        ldmx4(al, qlB + aoff);
#pragma unroll
        for (int np = 0; np < 4; np++) {
            unsigned bh[4], bl[4];
            unsigned boff = (unsigned)((np * 16 + bRow) * (SROW * 2) + kbb + bKb);
            ldmx4(bh, khB + boff);
            ldmx4(bl, klB + boff);
#pragma unroll
            for (int nj = 0; nj < 2; nj++) {
                int nt = np * 2 + nj;
                mma16816(sacc[nt], ah, &bh[nj * 2]);
                mma16816(sacc[nt], al, &bh[nj * 2]);
                mma16816(sacc[nt], ah, &bl[nj * 2]);
            }
        }
    }
    __syncthreads();

    const int cb = (lane & 3) * 2;
    float m0 = -1e30f, m1 = -1e30f;
#pragma unroll
    for (int nt = 0; nt < 8; nt++) {
        float k0 = msk[nt * 8 + cb], k1 = msk[nt * 8 + cb + 1];
        sacc[nt][0] += k0; sacc[nt][1] += k1;
        sacc[nt][2] += k0; sacc[nt][3] += k1;
        m0 = fmaxf(m0, fmaxf(sacc[nt][0], sacc[nt][1]));
        m1 = fmaxf(m1, fmaxf(sacc[nt][2], sacc[nt][3]));
    }
    m0 = fmaxf(m0, __shfl_xor_sync(0xffffffffu, m0, 1));
    m0 = fmaxf(m0, __shfl_xor_sync(0xffffffffu, m0, 2));
    m1 = fmaxf(m1, __shfl_xor_sync(0xffffffffu, m1, 1));
    m1 = fmaxf(m1, __shfl_xor_sync(0xffffffffu, m1, 2));

    float s0 = 0.0f, s1 = 0.0f;
#pragma unroll
    for (int nt = 0; nt < 8; nt++) {
        sacc[nt][0] = expf(sacc[nt][0] - m0); s0 += sacc[nt][0];
        sacc[nt][1] = expf(sacc[nt][1] - m0); s0 += sacc[nt][1];
        sacc[nt][2] = expf(sacc[nt][2] - m1); s1 += sacc[nt][2];
        sacc[nt][3] = expf(sacc[nt][3] - m1); s1 += sacc[nt][3];
    }
    s0 += __shfl_xor_sync(0xffffffffu, s0, 1);
    s0 += __shfl_xor_sync(0xffffffffu, s0, 2);
    s1 += __shfl_xor_sync(0xffffffffu, s1, 1);
    s1 += __shfl_xor_sync(0xffffffffu, s1, 2);
    float inv0 = 1.0f / s0, inv1 = 1.0f / s1;
#pragma unroll
    for (int nt = 0; nt < 8; nt++) {
        sacc[nt][0] *= inv0; sacc[nt][1] *= inv0;
        sacc[nt][2] *= inv1; sacc[nt][3] *= inv1;
    }

    const int r0 = wid * 16 + (lane >> 2);
    if (attn_out != nullptr) {
#pragma unroll
        for (int nt = 0; nt < 8; nt++) {
            *(float2*)&ls[r0 * 68 + nt * 8 + cb]       = make_float2(sacc[nt][0], sacc[nt][1]);
            *(float2*)&ls[(r0 + 8) * 68 + nt * 8 + cb] = make_float2(sacc[nt][2], sacc[nt][3]);
        }
    }

    float oacc[4][4];
#pragma unroll
    for (int nt = 0; nt < 4; nt++)
#pragma unroll
        for (int r = 0; r < 4; r++) oacc[nt][r] = 0.0f;

#pragma unroll
    for (int kt = 0; kt < 4; kt++) {
        float p00 = sacc[2 * kt][0],     p01 = sacc[2 * kt][1];
        float p02 = sacc[2 * kt][2],     p03 = sacc[2 * kt][3];
        float p10 = sacc[2 * kt + 1][0], p11 = sacc[2 * kt + 1][1];
        float p12 = sacc[2 * kt + 1][2], p13 = sacc[2 * kt + 1][3];
        unsigned ph[4], pl[4];
        ph[0] = pack_bf2(p00, p01); ph[1] = pack_bf2(p02, p03);
        ph[2] = pack_bf2(p10, p11); ph[3] = pack_bf2(p12, p13);
        pl[0] = pack_bf2(p00 - bf_round(p00), p01 - bf_round(p01));
        pl[1] = pack_bf2(p02 - bf_round(p02), p03 - bf_round(p03));
        pl[2] = pack_bf2(p10 - bf_round(p10), p11 - bf_round(p11));
        pl[3] = pack_bf2(p12 - bf_round(p12), p13 - bf_round(p13));
#pragma unroll
        for (int np = 0; np < 2; np++) {
            unsigned vh[4], vl[4];
            unsigned voff = (unsigned)((np * 16 + bRow) * (VROW * 2) + kt * 32 + bKb);
            ldmx4(vh, vhB + voff);
            ldmx4(vl, vlB + voff);
#pragma unroll
            for (int nj = 0; nj < 2; nj++) {
                int nt = np * 2 + nj;
                mma16816(oacc[nt], ph, &vh[nj * 2]);
                mma16816(oacc[nt], pl, &vh[nj * 2]);
                mma16816(oacc[nt], ph, &vl[nj * 2]);
            }
        }
    }

    {
        const int seq = head >> 3;
        const int hd  = head & 7;
#pragma unroll
        for (int nt = 0; nt < 4; nt++) {
            int dh = nt * 8 + cb;
            size_t base0 = ((size_t)(seq * TLEN + r0) * DMODEL) + hd * DHEAD + dh;
            size_t base1 = ((size_t)(seq * TLEN + r0 + 8) * DMODEL) + hd * DHEAD + dh;
            *(float2*)&g_ctx[base0] = make_float2(oacc[nt][0], oacc[nt][1]);
            *(float2*)&g_ctx[base1] = make_float2(oacc[nt][2], oacc[nt][3]);
        }
    }

    if (attn_out != nullptr) {
        __syncthreads();
        float* ap = attn_out + (size_t)head * (TLEN * TLEN);
#pragma unroll
        for (int i = 0; i < 32; i++) {
            int idx = tid + i * 128;
            ap[idx] = ls[(idx >> 6) * 68 + (idx & 63)];
        }
    }
}

// ---------------------------------------------------------------------------
extern "C" void kernel_launch(void* const* d_in, const int* in_sizes, int n_in,
                              void* d_out, int out_size)
{
    const float* v    = (const float*)d_in[0];
    const float* k    = (const float*)d_in[1];
    const float* q    = (const float*)d_in[2];
    const float* mask = (const float*)d_in[3];
    const float* wq_w = (const float*)d_in[4];
    const float* wq_b = (const float*)d_in[5];
    const float* wk_w = (const float*)d_in[6];
    const float* wk_b = (const float*)d_in[7];
    const float* wv_w = (const float*)d_in[8];
    const float* wv_b = (const float*)d_in[9];
    const float* wo_w = (const float*)d_in[10];
    const float* wo_b = (const float*)d_in[11];

    float* outp  = nullptr;
    float* attnp = nullptr;
    long osz = (long)out_size;
    if (osz >= OUT_ELEMS + ATTN_ELEMS) {
        outp  = (float*)d_out;
        attnp = (float*)d_out + OUT_ELEMS;
    } else if (osz == ATTN_ELEMS) {
        attnp = (float*)d_out;
        outp  = nullptr;
    } else {
        outp  = (float*)d_out;
        attnp = nullptr;
    }

    cudaFuncSetAttribute(qkv_mma_kernel,
                         cudaFuncAttributeMaxDynamicSharedMemorySize, SMEM_GEMM);
    cudaFuncSetAttribute(out_mma_kernel,
                         cudaFuncAttributeMaxDynamicSharedMemorySize, SMEM_GEMM);

    // 0) Weight transpose + bf16 hi/lo split (q-scale folded)
    prep_weights_kernel<<<4 * DMODEL * DMODEL / 256, 256>>>(wq_w, wk_w, wv_w, wo_w);

    // 1) QKV projections -> head-split bf16 hi/lo (pipelined, full-N tiles)
    dim3 g1(TOKENS / 128, 1, 3);
    qkv_mma_kernel<<<g1, 512, SMEM_GEMM>>>(q, k, v, wq_b, wk_b, wv_b);

    // 2) Tensor-core attention, 1 head per CTA
    attn_mma_kernel<<<SEQS * NHEADS, 128>>>(mask, attnp);

    // 3) Output projection (skip entirely if out isn't requested)
    if (outp != nullptr) {
        out_mma_kernel<<<TOKENS / 128, 512, SMEM_GEMM>>>(wo_b, outp);
    }
}

// round 17
// speedup vs baseline: 1.1880x; 1.1880x over previous
#include <cuda_runtime.h>
#include <cuda_bf16.h>
#include <cuda_fp16.h>
#include <math.h>

// Problem constants
#define DMODEL 256
#define TLEN   64
#define NHEADS 8
#define DHEAD  32
#define SEQS   1024                 // B*H*W
#define TOKENS (SEQS * TLEN)        // 65536
#define OUT_ELEMS  ((long)TOKENS * DMODEL)             // 16,777,216
#define ATTN_ELEMS ((long)SEQS * NHEADS * TLEN * TLEN) // 33,554,432
#define QSCALE 0.17677669529663687f                    // 1/sqrt(32)

// ---------------------------------------------------------------------------
// Device scratch (no allocation allowed). fp16 bits stored as ushort.
// ---------------------------------------------------------------------------
__device__ __align__(128) unsigned short g_q16[TOKENS * DMODEL]; // head-split
__device__ __align__(128) unsigned short g_k16[TOKENS * DMODEL];
__device__ __align__(128) unsigned short g_v16[TOKENS * DMODEL];
__device__ __align__(128) float g_ctx[TOKENS * DMODEL];          // merged heads
__device__ __align__(128) unsigned short g_wt[4][DMODEL * DMODEL]; // fp16 W^T

// ---------------------------------------------------------------------------
// Helpers (all baseline sm_80/90 PTX)
// ---------------------------------------------------------------------------
__device__ __forceinline__ unsigned smem_u32(const void* p) {
    unsigned a;
    asm("{ .reg .u64 t; cvta.to.shared.u64 t, %1; cvt.u32.u64 %0, t; }"
        : "=r"(a) : "l"(p));
    return a;
}
// pack two fp32 -> fp16x2 (e0 -> low half)
__device__ __forceinline__ unsigned pack_hf2(float e0, float e1) {
    __half2 h = __floats2half2_rn(e0, e1);   // x (=e0) is low half
    return *(unsigned*)&h;
}
__device__ __forceinline__ void ldmx4(unsigned* r, unsigned addr) {
    asm volatile("ldmatrix.sync.aligned.m8n8.x4.shared.b16 {%0,%1,%2,%3}, [%4];"
                 : "=r"(r[0]), "=r"(r[1]), "=r"(r[2]), "=r"(r[3]) : "r"(addr));
}
__device__ __forceinline__ void mma16816h(float* d, const unsigned* a, const unsigned* b) {
    asm volatile(
        "mma.sync.aligned.m16n8k16.row.col.f32.f16.f16.f32 "
        "{%0,%1,%2,%3}, {%4,%5,%6,%7}, {%8,%9}, {%0,%1,%2,%3};"
        : "+f"(d[0]), "+f"(d[1]), "+f"(d[2]), "+f"(d[3])
        : "r"(a[0]), "r"(a[1]), "r"(a[2]), "r"(a[3]), "r"(b[0]), "r"(b[1]));
}

// ---------------------------------------------------------------------------
// Weight prep: W[k][n] fp32 -> Wt[n][k] fp16 (transposed; q-scale folded)
// ---------------------------------------------------------------------------
__global__ void prep_weights_kernel(const float* __restrict__ wq,
                                    const float* __restrict__ wk,
                                    const float* __restrict__ wv,
                                    const float* __restrict__ wo)
{
    int i = blockIdx.x * 256 + threadIdx.x;      // 0 .. 4*65536-1
    int g = i >> 16;
    int r = i & 65535;
    int n = r >> 8;
    int k = r & 255;
    const float* W = (g == 0) ? wq : (g == 1) ? wk : (g == 2) ? wv : wo;
    float x = W[k * DMODEL + n];
    if (g == 0) x *= QSCALE;
    g_wt[g][(n << 8) | k] = __half_as_ushort(__float2half_rn(x));
}

// ---------------------------------------------------------------------------
// mma.sync fp16 single-term GEMM (R13 schedule):
//   C[65536 x 256] = A[65536 x 256] @ W_g[256 x 256] + bias
// CTA tile 128x128, 8 warps of 64x32. K chunked by 32 (two k16 steps).
// MODE 0: fp32 row-major store.  MODE 1: head-split fp16 store.
// smem rows padded to 40 halves (80B = 5x16B, coprime 8 -> conflict-free).
// ---------------------------------------------------------------------------
#define SROW 40

template <int MODE>
__device__ __forceinline__ void gemm_fp16(const float* __restrict__ A, int g,
                                          const float* __restrict__ bias,
                                          float bscale,
                                          float* __restrict__ Cf,
                                          unsigned short* __restrict__ Ch)
{
    __shared__ __align__(16) unsigned short Ah[128 * SROW];
    __shared__ __align__(16) unsigned short Bh[128 * SROW];
    __shared__ float sbias[DMODEL];

    const int tid  = threadIdx.x;
    const int lane = tid & 31;
    const int wid  = tid >> 5;
    const int m0   = blockIdx.y * 128;
    const int n0   = blockIdx.x * 128;
    const int warp_m = (wid >> 2) * 64;   // 0 or 64
    const int warp_n = (wid & 3) * 32;    // 0,32,64,96

    const unsigned short* __restrict__ WT = g_wt[g];

    sbias[tid] = bias[tid] * bscale;

    const unsigned ahB = smem_u32(Ah);
    const unsigned bhB = smem_u32(Bh);

    // ldmatrix lane-address components
    const int lg = lane >> 3;
    const int lr = lane & 7;
    const int aRow = lr + (lg & 1) * 8;
    const int aKb  = (lg >> 1) * 16;
    const int bRow = lr + (lg >> 1) * 8;
    const int bKb  = (lg & 1) * 16;

    float acc[4][4][4];
#pragma unroll
    for (int mi = 0; mi < 4; mi++)
#pragma unroll
        for (int ni = 0; ni < 4; ni++)
#pragma unroll
            for (int r = 0; r < 4; r++) acc[mi][ni][r] = 0.0f;

    for (int c = 0; c < 8; c++) {        // k chunks of 32
        const int k0 = c * 32;
        // --- A: 128 rows x 32 fp32 -> fp16 (1024 float4, 4/thread)
#pragma unroll
        for (int i = 0; i < 4; i++) {
            int idx = tid + i * 256;             // [0,1024)
            int row = idx >> 3;                  // [0,128)
            int c4  = idx & 7;                   // [0,8)
            float4 a = *(const float4*)&A[(size_t)(m0 + row) * DMODEL + k0 + c4 * 4];
            uint2 h = make_uint2(pack_hf2(a.x, a.y), pack_hf2(a.z, a.w));
            *(uint2*)&Ah[row * SROW + c4 * 4] = h;
        }
        // --- B: fp16 [n][k]: 128 rows x 32 halves (512 uint4, 2/thread)
#pragma unroll
        for (int i = 0; i < 2; i++) {
            int idx = tid + i * 256;             // [0,512)
            int row = idx >> 2;                  // [0,128)
            int u   = idx & 3;                   // 16B unit
            uint4 w = *(const uint4*)&WT[(size_t)(n0 + row) * DMODEL + k0 + u * 8];
            *(uint4*)&Bh[row * SROW + u * 8] = w;
        }
        __syncthreads();

#pragma unroll
        for (int ks = 0; ks < 2; ks++) {
            const int kbb = ks * 32;             // byte offset of k16 step
            unsigned afh[4][4];
#pragma unroll
            for (int mi = 0; mi < 4; mi++) {
                unsigned off = (unsigned)((warp_m + mi * 16 + aRow) * (SROW * 2) + kbb + aKb);
                ldmx4(afh[mi], ahB + off);
            }
#pragma unroll
            for (int pair = 0; pair < 2; pair++) {
                unsigned bfh[4];
                unsigned off = (unsigned)((warp_n + pair * 16 + bRow) * (SROW * 2) + kbb + bKb);
                ldmx4(bfh, bhB + off);
#pragma unroll
                for (int mi = 0; mi < 4; mi++) {
#pragma unroll
                    for (int nj = 0; nj < 2; nj++) {
                        mma16816h(acc[mi][pair * 2 + nj], afh[mi], &bfh[nj * 2]);
                    }
                }
            }
        }
        __syncthreads();
    }

    // Epilogue: C-fragment thread t holds (row = t/4 [+8], col = 2*(t%4)+{0,1})
    const int qr = lane >> 2;
    const int qc = (lane & 3) * 2;
#pragma unroll
    for (int mi = 0; mi < 4; mi++) {
#pragma unroll
        for (int ni = 0; ni < 4; ni++) {
            int colg = n0 + warp_n + ni * 8 + qc;
            float b0 = sbias[colg], b1 = sbias[colg + 1];
            int r0 = m0 + warp_m + mi * 16 + qr;
            int r1 = r0 + 8;
            float x00 = acc[mi][ni][0] + b0, x01 = acc[mi][ni][1] + b1;
            float x10 = acc[mi][ni][2] + b0, x11 = acc[mi][ni][3] + b1;
            if (MODE == 0) {
                *(float2*)&Cf[(size_t)r0 * DMODEL + colg] = make_float2(x00, x01);
                *(float2*)&Cf[(size_t)r1 * DMODEL + colg] = make_float2(x10, x11);
            } else {
                int hd = colg >> 5;
                int dh = colg & 31;
                int s0 = r0 >> 6, t0 = r0 & 63;
                int s1 = r1 >> 6, t1 = r1 & 63;
                size_t b0i = (((size_t)s0 * NHEADS + hd) * TLEN + t0) * DHEAD + dh;
                size_t b1i = (((size_t)s1 * NHEADS + hd) * TLEN + t1) * DHEAD + dh;
                ushort2 h;
                h.x = __half_as_ushort(__float2half_rn(x00));
                h.y = __half_as_ushort(__float2half_rn(x01));
                *(ushort2*)&Ch[b0i] = h;
                h.x = __half_as_ushort(__float2half_rn(x10));
                h.y = __half_as_ushort(__float2half_rn(x11));
                *(ushort2*)&Ch[b1i] = h;
            }
        }
    }
}

__global__ void __launch_bounds__(256, 2)
qkv_mma_kernel(const float* __restrict__ q, const float* __restrict__ k,
               const float* __restrict__ v,
               const float* __restrict__ bq, const float* __restrict__ bk,
               const float* __restrict__ bv)
{
    int z = blockIdx.z;
    if (z == 0)      gemm_fp16<1>(q, 0, bq, QSCALE, nullptr, g_q16);
    else if (z == 1) gemm_fp16<1>(k, 1, bk, 1.0f,  nullptr, g_k16);
    else             gemm_fp16<1>(v, 2, bv, 1.0f,  nullptr, g_v16);
}

__global__ void __launch_bounds__(256, 2)
out_mma_kernel(const float* __restrict__ bo, float* __restrict__ C)
{
    gemm_fp16<0>(g_ctx, 3, bo, 1.0f, C, nullptr);
}

// ---------------------------------------------------------------------------
// Tensor-core attention (R13 structure, fp16 single-term):
// 1 head per CTA, 128 threads (4 warps of 16 q-rows).
// S = Q@K^T (fp16, fp32 acc); register softmax (quad shfl);
// P packed fp16 C-frag -> A-frag; O = P@V.
// V transposed in smem [dh][s], pitch 72 (9x16B, coprime 8).
// ---------------------------------------------------------------------------
#define VROW 72

__global__ void __launch_bounds__(128)
attn_mma_kernel(const float* __restrict__ mask, float* __restrict__ attn_out)
{
    __shared__ __align__(16) char sm[29952];
    unsigned short* Qh  = (unsigned short*)(sm);            // 64 x SROW fp16
    unsigned short* Kh  = (unsigned short*)(sm + 5120);     // 64 x SROW fp16
    float*          ls  = (float*)(sm);                     // overlay (17408 <= 20480)
    unsigned short* Vth = (unsigned short*)(sm + 20480);    // 32 x VROW fp16
    float*          msk = (float*)(sm + 29696);             // 64 floats

    const int head = blockIdx.x;          // seq*NH + n
    const int tid  = threadIdx.x;
    const int lane = tid & 31;
    const int wid  = tid >> 5;
    const int b    = head >> 11;

    if (tid < 64) msk[tid] = mask[b * 64 + tid] * (-1e9f);

    const size_t hb = (size_t)head * (TLEN * DHEAD);

    // Load Q,K: 256 uint4 each, 2 per thread
#pragma unroll
    for (int i = 0; i < 2; i++) {
        int idx = tid + i * 128;          // [0,256)
        int r = idx >> 2;
        int u = idx & 3;
        unsigned off = (unsigned)(r * (SROW * 2) + u * 16);
        *(uint4*)((char*)Qh + off) = ((const uint4*)(g_q16 + hb))[idx];
        *(uint4*)((char*)Kh + off) = ((const uint4*)(g_k16 + hb))[idx];
    }
    // Transpose V into [dh][s]
#pragma unroll
    for (int i = 0; i < 16; i++) {
        int idx = tid + i * 128;          // [0,2048)
        int s  = idx >> 5;
        int dh = idx & 31;
        Vth[dh * VROW + s] = g_v16[hb + idx];
    }
    __syncthreads();

    const unsigned qhB = smem_u32(Qh);
    const unsigned khB = smem_u32(Kh);
    const unsigned vhB = smem_u32(Vth);

    const int lg = lane >> 3;
    const int lr = lane & 7;
    const int aRow = lr + (lg & 1) * 8;
    const int aKb  = (lg >> 1) * 16;
    const int bRow = lr + (lg >> 1) * 8;
    const int bKb  = (lg & 1) * 16;

    // ---- S = Q @ K^T. Warp covers rows [16*wid, +16), all 64 cols.
    float sacc[8][4];
#pragma unroll
    for (int nt = 0; nt < 8; nt++)
#pragma unroll
        for (int r = 0; r < 4; r++) sacc[nt][r] = 0.0f;

#pragma unroll
    for (int ks = 0; ks < 2; ks++) {
        const int kbb = ks * 32;
        unsigned ah[4];
        unsigned aoff = (unsigned)((wid * 16 + aRow) * (SROW * 2) + kbb + aKb);
        ldmx4(ah, qhB + aoff);
#pragma unroll
        for (int np = 0; np < 4; np++) {
            unsigned bh[4];
            unsigned boff = (unsigned)((np * 16 + bRow) * (SROW * 2) + kbb + bKb);
            ldmx4(bh, khB + boff);
#pragma unroll
            for (int nj = 0; nj < 2; nj++) {
                mma16816h(sacc[np * 2 + nj], ah, &bh[nj * 2]);
            }
        }
    }
    __syncthreads();   // Q/K smem dead; ls overlay becomes writable

    // ---- mask + softmax (rows r0 = 16*wid + lane/4 and r0+8)
    const int cb = (lane & 3) * 2;
    float m0 = -1e30f, m1 = -1e30f;
#pragma unroll
    for (int nt = 0; nt < 8; nt++) {
        float k0 = msk[nt * 8 + cb], k1 = msk[nt * 8 + cb + 1];
        sacc[nt][0] += k0; sacc[nt][1] += k1;
        sacc[nt][2] += k0; sacc[nt][3] += k1;
        m0 = fmaxf(m0, fmaxf(sacc[nt][0], sacc[nt][1]));
        m1 = fmaxf(m1, fmaxf(sacc[nt][2], sacc[nt][3]));
    }
    m0 = fmaxf(m0, __shfl_xor_sync(0xffffffffu, m0, 1));
    m0 = fmaxf(m0, __shfl_xor_sync(0xffffffffu, m0, 2));
    m1 = fmaxf(m1, __shfl_xor_sync(0xffffffffu, m1, 1));
    m1 = fmaxf(m1, __shfl_xor_sync(0xffffffffu, m1, 2));

    float s0 = 0.0f, s1 = 0.0f;
#pragma unroll
    for (int nt = 0; nt < 8; nt++) {
        sacc[nt][0] = expf(sacc[nt][0] - m0); s0 += sacc[nt][0];
        sacc[nt][1] = expf(sacc[nt][1] - m0); s0 += sacc[nt][1];
        sacc[nt][2] = expf(sacc[nt][2] - m1); s1 += sacc[nt][2];
        sacc[nt][3] = expf(sacc[nt][3] - m1); s1 += sacc[nt][3];
    }
    s0 += __shfl_xor_sync(0xffffffffu, s0, 1);
    s0 += __shfl_xor_sync(0xffffffffu, s0, 2);
    s1 += __shfl_xor_sync(0xffffffffu, s1, 1);
    s1 += __shfl_xor_sync(0xffffffffu, s1, 2);
    float inv0 = 1.0f / s0, inv1 = 1.0f / s1;
#pragma unroll
    for (int nt = 0; nt < 8; nt++) {
        sacc[nt][0] *= inv0; sacc[nt][1] *= inv0;
        sacc[nt][2] *= inv1; sacc[nt][3] *= inv1;
    }

    const int r0 = wid * 16 + (lane >> 2);
    // Stage P for the attn output (only if requested)
    if (attn_out != nullptr) {
#pragma unroll
        for (int nt = 0; nt < 8; nt++) {
            *(float2*)&ls[r0 * 68 + nt * 8 + cb]       = make_float2(sacc[nt][0], sacc[nt][1]);
            *(float2*)&ls[(r0 + 8) * 68 + nt * 8 + cb] = make_float2(sacc[nt][2], sacc[nt][3]);
        }
    }

    // ---- O = P @ V, P fragments packed fp16 from sacc
    float oacc[4][4];
#pragma unroll
    for (int nt = 0; nt < 4; nt++)
#pragma unroll
        for (int r = 0; r < 4; r++) oacc[nt][r] = 0.0f;

#pragma unroll
    for (int kt = 0; kt < 4; kt++) {
        unsigned ph[4];
        ph[0] = pack_hf2(sacc[2 * kt][0],     sacc[2 * kt][1]);
        ph[1] = pack_hf2(sacc[2 * kt][2],     sacc[2 * kt][3]);
        ph[2] = pack_hf2(sacc[2 * kt + 1][0], sacc[2 * kt + 1][1]);
        ph[3] = pack_hf2(sacc[2 * kt + 1][2], sacc[2 * kt + 1][3]);
#pragma unroll
        for (int np = 0; np < 2; np++) {
            unsigned vh[4];
            unsigned voff = (unsigned)((np * 16 + bRow) * (VROW * 2) + kt * 32 + bKb);
            ldmx4(vh, vhB + voff);
#pragma unroll
            for (int nj = 0; nj < 2; nj++) {
                mma16816h(oacc[np * 2 + nj], ph, &vh[nj * 2]);
            }
        }
    }

    // ---- write ctx (merged heads, fp32)
    {
        const int seq = head >> 3;
        const int hd  = head & 7;
#pragma unroll
        for (int nt = 0; nt < 4; nt++) {
            int dh = nt * 8 + cb;
            size_t base0 = ((size_t)(seq * TLEN + r0) * DMODEL) + hd * DHEAD + dh;
            size_t base1 = ((size_t)(seq * TLEN + r0 + 8) * DMODEL) + hd * DHEAD + dh;
            *(float2*)&g_ctx[base0] = make_float2(oacc[nt][0], oacc[nt][1]);
            *(float2*)&g_ctx[base1] = make_float2(oacc[nt][2], oacc[nt][3]);
        }
    }

    // ---- coalesced attn-probs write
    if (attn_out != nullptr) {
        __syncthreads();
        float* ap = attn_out + (size_t)head * (TLEN * TLEN);
#pragma unroll
        for (int i = 0; i < 32; i++) {
            int idx = tid + i * 128;      // [0,4096)
            ap[idx] = ls[(idx >> 6) * 68 + (idx & 63)];
        }
    }
}

// ---------------------------------------------------------------------------
extern "C" void kernel_launch(void* const* d_in, const int* in_sizes, int n_in,
                              void* d_out, int out_size)
{
    const float* v    = (const float*)d_in[0];
    const float* k    = (const float*)d_in[1];
    const float* q    = (const float*)d_in[2];
    const float* mask = (const float*)d_in[3];
    const float* wq_w = (const float*)d_in[4];
    const float* wq_b = (const float*)d_in[5];
    const float* wk_w = (const float*)d_in[6];
    const float* wk_b = (const float*)d_in[7];
    const float* wv_w = (const float*)d_in[8];
    const float* wv_b = (const float*)d_in[9];
    const float* wo_w = (const float*)d_in[10];
    const float* wo_b = (const float*)d_in[11];

    float* outp  = nullptr;
    float* attnp = nullptr;
    long osz = (long)out_size;
    if (osz >= OUT_ELEMS + ATTN_ELEMS) {
        outp  = (float*)d_out;
        attnp = (float*)d_out + OUT_ELEMS;
    } else if (osz == ATTN_ELEMS) {
        attnp = (float*)d_out;
        outp  = nullptr;
    } else {
        outp  = (float*)d_out;
        attnp = nullptr;
    }

    // 0) Weight transpose to fp16 (q-scale folded)
    prep_weights_kernel<<<4 * DMODEL * DMODEL / 256, 256>>>(wq_w, wk_w, wv_w, wo_w);

    // 1) QKV projections -> head-split fp16
    dim3 g1(DMODEL / 128, TOKENS / 128, 3);
    qkv_mma_kernel<<<g1, 256>>>(q, k, v, wq_b, wk_b, wv_b);

    // 2) Tensor-core attention, 1 head per CTA
    attn_mma_kernel<<<SEQS * NHEADS, 128>>>(mask, attnp);

    // 3) Output projection (skip entirely if out isn't requested)
    if (outp != nullptr) {
        dim3 g2(DMODEL / 128, TOKENS / 128);
        out_mma_kernel<<<g2, 256>>>(wo_b, outp);
    }
}